// round 14
// baseline (speedup 1.0000x reference)
#include <cuda_runtime.h>

// BetterBot round-14: R13 structure, but lookup tables (Wexp/t0v/embp/Wout)
// read DIRECTLY from global (L1D-resident, ~12KB hot) — per-block shared
// staging deleted (~190 LSU instr/warp saved). Shared keeps only the dynamic
// layer-1 kv exchange + id bytes. Uniform weights stay in __constant__.

#define TPB 256
#define NW  8
#define SPB 16   // samples per block

typedef unsigned long long u64;
typedef ulonglong2 u64x2;

__device__ __forceinline__ u64 pk2(float lo, float hi) {
    u64 r; asm("mov.b64 %0,{%1,%2};" : "=l"(r) : "f"(lo), "f"(hi)); return r;
}
__device__ __forceinline__ void upk2(u64 v, float &lo, float &hi) {
    asm("mov.b64 {%0,%1},%2;" : "=f"(lo), "=f"(hi) : "l"(v));
}
__device__ __forceinline__ u64 ffma2(u64 a, u64 b, u64 c) {
    u64 d; asm("fma.rn.f32x2 %0,%1,%2,%3;" : "=l"(d) : "l"(a), "l"(b), "l"(c)); return d;
}
__device__ __forceinline__ u64 fmul2(u64 a, u64 b) {
    u64 d; asm("mul.rn.f32x2 %0,%1,%2;" : "=l"(d) : "l"(a), "l"(b)); return d;
}
__device__ __forceinline__ u64 fadd2(u64 a, u64 b) {
    u64 d; asm("add.rn.f32x2 %0,%1,%2;" : "=l"(d) : "l"(a), "l"(b)); return d;
}
__device__ __forceinline__ float ex2f(float x) {
    float r; asm("ex2.approx.f32 %0,%1;" : "=f"(r) : "f"(x)); return r;
}
__device__ __forceinline__ float rcpf(float x) {
    float r; asm("rcp.approx.f32 %0,%1;" : "=f"(r) : "f"(x)); return r;
}

struct Params {
    const int   *dt, *ds, *sl;
    const float *emb_dice, *emb_star, *emb_btns;
    const float *Wqkv[2], *bqkv[2], *Wo[2], *bo[2], *Wl[2], *bl[2];
    const float *Wout, *bout;
    float *out;
    int B;
};

// Warp-uniform weights -> constant bank (ULDC path).
struct __align__(16) GC {
    u64x2 Wq1[12][4];    // layer-1 Wqkv row pairs; q rows pre-scaled by S
    u64   bq1[12];
    u64x2 Wo2[2][4][4];  // row pairs (2p, 2p+1)
    u64   bo2[2][4];
    u64x2 Wl2[2][4][4];
    u64   bl2[2][4];
};
__constant__ GC gcw;
__device__ GC g_gc;      // prep output, memcpy'd into gcw

// Per-lane-indexed tables -> global, L1D-resident (read directly, NOT staged).
struct __align__(16) GW {
    u64 Wexp[32][33];    // [id_k][id_q] packed per-head exp'd scores
    u64 t0v[32][6];      // layer-0 v pairs; 48B stride
    u64 embp[32][6];     // x pairs (48B stride)
    u64 Wout2[20][4];    // pre-scaled by 1/15
    float bout[20];
    float pad[4];
};
__device__ GW g_w;
__device__ u64 g_q0[32][4];   // prep staging
__device__ u64 g_k0[32][4];

__global__ void prep_kernel(Params p) {
    const int i = threadIdx.x;
    const float S = 0.72134752f;   // 0.5 * log2(e)

    // ---------- phase 1 ----------
    if (i < 384) {
        int id = i / 12, pp = i % 12;
        int gg = pp >> 2, r = pp & 3;
        int r0 = gg * 8 + r, r1 = r0 + 4;
        const float *e = (id < 15) ? p.emb_dice + id * 8
                        : (id < 30) ? p.emb_star + (id - 15) * 8
                                    : p.emb_btns + (id - 30) * 8;
        const float *w0 = p.Wqkv[0] + r0 * 8;
        const float *w1 = p.Wqkv[0] + r1 * 8;
        u64 acc = pk2(p.bqkv[0][r0], p.bqkv[0][r1]);
        #pragma unroll
        for (int j = 0; j < 8; j++)
            acc = ffma2(pk2(e[j], e[j]), pk2(w0[j], w1[j]), acc);
        if (pp < 4)      g_q0[id][pp]     = fmul2(acc, pk2(S, S));
        else if (pp < 8) g_k0[id][pp - 4] = acc;
        else             g_w.t0v[id][pp - 8] = acc;
    } else if (i < 480) {            // Wq1 (q rows S-scaled)
        int k = i - 384; int pp = k >> 3, j = k & 7;
        int gg = pp >> 2, r = pp & 3, r0 = gg * 8 + r, r1 = r0 + 4;
        u64 w = pk2(p.Wqkv[1][r0 * 8 + j], p.Wqkv[1][r1 * 8 + j]);
        if (pp < 4) w = fmul2(w, pk2(S, S));
        ((u64 *)g_gc.Wq1)[pp * 8 + j] = w;
    } else if (i < 492) {            // bq1
        int pp = i - 480; int gg = pp >> 2, r = pp & 3, r0 = gg * 8 + r;
        u64 w = pk2(p.bqkv[1][r0], p.bqkv[1][r0 + 4]);
        if (pp < 4) w = fmul2(w, pk2(S, S));
        g_gc.bq1[pp] = w;
    } else if (i < 556) {            // Wo2 (flat [l][pr][j])
        int k = i - 492; int l = k >> 5, pr = (k >> 3) & 3, j = k & 7;
        ((u64 *)g_gc.Wo2)[k] = pk2(p.Wo[l][2 * pr * 8 + j], p.Wo[l][(2 * pr + 1) * 8 + j]);
    } else if (i < 564) {            // bo2
        int k = i - 556; int l = k >> 2, pr = k & 3;
        g_gc.bo2[l][pr] = pk2(p.bo[l][2 * pr], p.bo[l][2 * pr + 1]);
    } else if (i < 628) {            // Wl2
        int k = i - 564; int l = k >> 5, pr = (k >> 3) & 3, j = k & 7;
        ((u64 *)g_gc.Wl2)[k] = pk2(p.Wl[l][2 * pr * 8 + j], p.Wl[l][(2 * pr + 1) * 8 + j]);
    } else if (i < 636) {            // bl2
        int k = i - 628; int l = k >> 2, pr = k & 3;
        g_gc.bl2[l][pr] = pk2(p.bl[l][2 * pr], p.bl[l][2 * pr + 1]);
    } else if (i < 716) {            // Wout2 pre-scaled by 1/15
        int k = i - 636; int a = k >> 2, j = k & 3;
        const float m = 1.0f / 15.0f;
        g_w.Wout2[a][j] = pk2(p.Wout[a * 8 + 2 * j] * m, p.Wout[a * 8 + 2 * j + 1] * m);
    } else if (i < 736) {
        g_w.bout[i - 716] = p.bout[i - 716];
    } else if (i < 992) {            // embp
        int k = i - 736; int id = k >> 3, j = k & 7;
        const float *e = (id < 15) ? p.emb_dice + id * 8
                        : (id < 30) ? p.emb_star + (id - 15) * 8
                                    : p.emb_btns + (id - 30) * 8;
        ((float *)g_w.embp[id])[j] = e[j];
    }
    __syncthreads();

    // ---------- phase 2: Wexp ----------
    {
        int a = i >> 5, b = i & 31;   // a = query id, b = key id
        u64 s2 = 0;
        #pragma unroll
        for (int j = 0; j < 4; j++)
            s2 = ffma2(g_q0[a][j], g_k0[b][j], s2);
        float s0, s1; upk2(s2, s0, s1);
        g_w.Wexp[b][a] = pk2(ex2f(s0), ex2f(s1));
    }
}

// o-proj + residual + MLP + residual; weights from constant bank (l literal).
__device__ __forceinline__ void ff1(const float *o, float *x, const int l) {
    u64 od[8];
    #pragma unroll
    for (int i = 0; i < 8; i++) od[i] = pk2(o[i], o[i]);
    float xo[8];
    #pragma unroll
    for (int pr = 0; pr < 4; pr++) {
        u64x2 w01 = gcw.Wo2[l][pr][0], w23 = gcw.Wo2[l][pr][1];
        u64x2 w45 = gcw.Wo2[l][pr][2], w67 = gcw.Wo2[l][pr][3];
        u64 acc = ffma2(od[0], w01.x, gcw.bo2[l][pr]);
        acc = ffma2(od[1], w01.y, acc); acc = ffma2(od[2], w23.x, acc);
        acc = ffma2(od[3], w23.y, acc); acc = ffma2(od[4], w45.x, acc);
        acc = ffma2(od[5], w45.y, acc); acc = ffma2(od[6], w67.x, acc);
        acc = ffma2(od[7], w67.y, acc);
        float r0, r1; upk2(acc, r0, r1);
        xo[2 * pr] = x[2 * pr] + r0; xo[2 * pr + 1] = x[2 * pr + 1] + r1;
    }
    u64 xd[8];
    #pragma unroll
    for (int i = 0; i < 8; i++) xd[i] = pk2(xo[i], xo[i]);
    #pragma unroll
    for (int pr = 0; pr < 4; pr++) {
        u64x2 w01 = gcw.Wl2[l][pr][0], w23 = gcw.Wl2[l][pr][1];
        u64x2 w45 = gcw.Wl2[l][pr][2], w67 = gcw.Wl2[l][pr][3];
        u64 acc = ffma2(xd[0], w01.x, gcw.bl2[l][pr]);
        acc = ffma2(xd[1], w01.y, acc); acc = ffma2(xd[2], w23.x, acc);
        acc = ffma2(xd[3], w23.y, acc); acc = ffma2(xd[4], w45.x, acc);
        acc = ffma2(xd[5], w45.y, acc); acc = ffma2(xd[6], w67.x, acc);
        acc = ffma2(xd[7], w67.y, acc);
        float r0, r1; upk2(acc, r0, r1);
        x[2 * pr]     = xo[2 * pr]     + fmaxf(r0, 0.f);
        x[2 * pr + 1] = xo[2 * pr + 1] + fmaxf(r1, 0.f);
    }
}

__global__ void __launch_bounds__(TPB, 4) bot_kernel(Params p) {
    // ONLY the dynamic kv exchange lives in shared now.
    // layer-1 kv: [warp][half][168 u64]; half stride 1344 B (%128==64 ->
    // conflict-free vs other half). token row = 10 u64: k01,k23,v01,v23,pad2.
    __shared__ __align__(16) u64 kvs[NW][2][168];         // 21504 B
    __shared__ __align__(16) unsigned char idsb[NW][2][16];

    const int tid = threadIdx.x;
    const int warp = tid >> 5, lane = tid & 31;
    const int half = lane >> 4, s = lane & 15;
    const int b = blockIdx.x * SPB + warp * 2 + half;
    const bool tok = (s < 15);

    int id = 0;   // lane-15 dummy (slot 15 never read)
    if (tok) {
        const int base = b * 5;
        id = (s < 5) ? p.dt[base + s]
           : (s < 10) ? 15 + p.ds[base + s - 5]
                      : 30 + p.sl[base + s - 10];
    }
    idsb[warp][half][s] = (unsigned char)id;
    __syncwarp();
    const uint4 idw = *(const uint4 *)&idsb[warp][half][0];

    float x[8];
    {
        const u64x2 *e = (const u64x2 *)&g_w.embp[id][0];
        u64x2 e01 = e[0], e23 = e[1];
        upk2(e01.x, x[0], x[1]); upk2(e01.y, x[2], x[3]);
        upk2(e23.x, x[4], x[5]); upk2(e23.y, x[6], x[7]);
    }

    // ---- layer 0 attention: pure table reads (L1D-resident), no q/k ----
    {
        u64 sum2 = 0, av0 = 0, av1 = 0, av2 = 0, av3 = 0;
        #pragma unroll
        for (int t = 0; t < 15; t++) {
            unsigned idt = ((&idw.x)[t >> 2] >> ((t & 3) * 8)) & 0xFF;
            const u64 *wrow = (const u64 *)((const char *)g_w.Wexp + idt * 264);
            u64 w = wrow[id];                       // LDG.64 gather by own id
            const u64x2 *vp = (const u64x2 *)&g_w.t0v[idt][0];
            u64x2 v01 = vp[0], v23 = vp[1];         // half-uniform
            sum2 = fadd2(sum2, w);
            av0 = ffma2(w, v01.x, av0); av1 = ffma2(w, v01.y, av1);
            av2 = ffma2(w, v23.x, av2); av3 = ffma2(w, v23.y, av3);
        }
        float s0, s1; upk2(sum2, s0, s1);
        u64 inv = pk2(rcpf(s0), rcpf(s1));
        float o[8];
        { u64 t = fmul2(av0, inv); upk2(t, o[0], o[4]); }
        { u64 t = fmul2(av1, inv); upk2(t, o[1], o[5]); }
        { u64 t = fmul2(av2, inv); upk2(t, o[2], o[6]); }
        { u64 t = fmul2(av3, inv); upk2(t, o[3], o[7]); }
        ff1(o, x, 0);
    }

    // ---- layer 1: qkv gemv (constant weights) -> kv exchange -> attention ----
    u64 *kvh = &kvs[warp][half][0];
    u64 *row = kvh + s * 10;
    u64 q2[4];
    {
        u64 xd[8];
        #pragma unroll
        for (int i = 0; i < 8; i++) xd[i] = pk2(x[i], x[i]);
        u64 hold = 0;
        #pragma unroll
        for (int pr = 0; pr < 12; pr++) {
            u64x2 w01 = gcw.Wq1[pr][0], w23 = gcw.Wq1[pr][1];
            u64x2 w45 = gcw.Wq1[pr][2], w67 = gcw.Wq1[pr][3];
            u64 a = ffma2(xd[0], w01.x, gcw.bq1[pr]);
            a = ffma2(xd[1], w01.y, a); a = ffma2(xd[2], w23.x, a);
            a = ffma2(xd[3], w23.y, a); a = ffma2(xd[4], w45.x, a);
            a = ffma2(xd[5], w45.y, a); a = ffma2(xd[6], w67.x, a);
            a = ffma2(xd[7], w67.y, a);
            if (pr < 4) q2[pr] = a;
            else if ((pr & 1) == 0) hold = a;
            else if (tok) {
                u64x2 st; st.x = hold; st.y = a;
                *(u64x2 *)(row + (pr - 5)) = st;   // offsets 0,2,4,6
            }
        }
    }
    __syncwarp();   // kv writes -> kv reads
    {
        u64 sum2 = 0, av0 = 0, av1 = 0, av2 = 0, av3 = 0;
        #pragma unroll
        for (int t = 0; t < 15; t++) {
            const u64 *r = kvh + t * 10;
            u64x2 k01 = *(const u64x2 *)(r);
            u64x2 k23 = *(const u64x2 *)(r + 2);
            u64 s2 = fmul2(q2[0], k01.x);
            s2 = ffma2(q2[1], k01.y, s2);
            s2 = ffma2(q2[2], k23.x, s2);
            s2 = ffma2(q2[3], k23.y, s2);
            float f0, f1; upk2(s2, f0, f1);
            u64 w = pk2(ex2f(f0), ex2f(f1));
            u64x2 v01 = *(const u64x2 *)(r + 4);
            u64x2 v23 = *(const u64x2 *)(r + 6);
            sum2 = fadd2(sum2, w);
            av0 = ffma2(w, v01.x, av0); av1 = ffma2(w, v01.y, av1);
            av2 = ffma2(w, v23.x, av2); av3 = ffma2(w, v23.y, av3);
        }
        float s0, s1; upk2(sum2, s0, s1);
        u64 inv = pk2(rcpf(s0), rcpf(s1));
        float o[8];
        { u64 t = fmul2(av0, inv); upk2(t, o[0], o[4]); }
        { u64 t = fmul2(av1, inv); upk2(t, o[1], o[5]); }
        { u64 t = fmul2(av2, inv); upk2(t, o[2], o[6]); }
        { u64 t = fmul2(av3, inv); upk2(t, o[3], o[7]); }
        ff1(o, x, 1);
    }

    // ---- sum over 15 tokens (1/15 folded into Wout) ----
    #pragma unroll
    for (int j = 0; j < 8; j++) {
        float v = tok ? x[j] : 0.f;
        v += __shfl_xor_sync(0xffffffffu, v, 1);
        v += __shfl_xor_sync(0xffffffffu, v, 2);
        v += __shfl_xor_sync(0xffffffffu, v, 4);
        v += __shfl_xor_sync(0xffffffffu, v, 8);
        x[j] = v;
    }

    // ---- output projection (tables from L1D-resident global) ----
    if (b < p.B) {
        u64 xq[4];
        #pragma unroll
        for (int i = 0; i < 4; i++) xq[i] = pk2(x[2 * i], x[2 * i + 1]);
        {
            const u64x2 *wp = (const u64x2 *)g_w.Wout2[s];
            u64x2 w01 = wp[0], w23 = wp[1];
            u64 acc = fmul2(xq[0], w01.x);
            acc = ffma2(xq[1], w01.y, acc);
            acc = ffma2(xq[2], w23.x, acc);
            acc = ffma2(xq[3], w23.y, acc);
            float r0, r1; upk2(acc, r0, r1);
            p.out[b * 20 + s] = g_w.bout[s] + r0 + r1;
        }
        if (s < 4) {
            const int a = s + 16;
            const u64x2 *wp = (const u64x2 *)g_w.Wout2[a];
            u64x2 w01 = wp[0], w23 = wp[1];
            u64 acc = fmul2(xq[0], w01.x);
            acc = ffma2(xq[1], w01.y, acc);
            acc = ffma2(xq[2], w23.x, acc);
            acc = ffma2(xq[3], w23.y, acc);
            float r0, r1; upk2(acc, r0, r1);
            p.out[b * 20 + a] = g_w.bout[a] + r0 + r1;
        }
    }
}

extern "C" void kernel_launch(void* const* d_in, const int* in_sizes, int n_in,
                              void* d_out, int out_size) {
    Params p;
    p.dt = (const int *)d_in[0];
    p.ds = (const int *)d_in[1];
    p.sl = (const int *)d_in[2];
    p.emb_dice = (const float *)d_in[3];
    p.emb_star = (const float *)d_in[4];
    p.emb_btns = (const float *)d_in[5];

    int layer_base, wout_i, bout_i;
    if (in_sizes[6] == 160) { wout_i = 6; bout_i = 7; layer_base = 8; }
    else                    { layer_base = 6; wout_i = 18; bout_i = 19; }

    for (int l = 0; l < 2; l++) {
        int o = layer_base + 6 * l;
        p.Wqkv[l] = (const float *)d_in[o];
        p.bqkv[l] = (const float *)d_in[o + 1];
        p.Wo[l]   = (const float *)d_in[o + 2];
        p.bo[l]   = (const float *)d_in[o + 3];
        p.Wl[l]   = (const float *)d_in[o + 4];
        p.bl[l]   = (const float *)d_in[o + 5];
    }
    p.Wout = (const float *)d_in[wout_i];
    p.bout = (const float *)d_in[bout_i];
    p.out  = (float *)d_out;
    p.B    = in_sizes[0] / 5;

    prep_kernel<<<1, 1024>>>(p);

    // D2D copy of packed uniform weights into the constant bank (capturable).
    void *gc_src = nullptr;
    cudaGetSymbolAddress(&gc_src, g_gc);
    cudaMemcpyToSymbolAsync(gcw, gc_src, sizeof(GC), 0, cudaMemcpyDeviceToDevice, 0);

    int blocks = (p.B + SPB - 1) / SPB;
    bot_kernel<<<blocks, TPB>>>(p);
}

// round 15
// speedup vs baseline: 1.2842x; 1.2842x over previous
#include <cuda_runtime.h>

// BetterBot round-15: R9 verbatim (best measured: 53.8us) + mean-pool in
// packed f32x2 pair domain (16 fadd2 replaces 32 FADD). Nothing else changed.

#define TPB 256
#define NW  8
#define SPB 16   // samples per block

typedef unsigned long long u64;
typedef ulonglong2 u64x2;

__device__ __forceinline__ u64 pk2(float lo, float hi) {
    u64 r; asm("mov.b64 %0,{%1,%2};" : "=l"(r) : "f"(lo), "f"(hi)); return r;
}
__device__ __forceinline__ void upk2(u64 v, float &lo, float &hi) {
    asm("mov.b64 {%0,%1},%2;" : "=f"(lo), "=f"(hi) : "l"(v));
}
__device__ __forceinline__ u64 ffma2(u64 a, u64 b, u64 c) {
    u64 d; asm("fma.rn.f32x2 %0,%1,%2,%3;" : "=l"(d) : "l"(a), "l"(b), "l"(c)); return d;
}
__device__ __forceinline__ u64 fmul2(u64 a, u64 b) {
    u64 d; asm("mul.rn.f32x2 %0,%1,%2;" : "=l"(d) : "l"(a), "l"(b)); return d;
}
__device__ __forceinline__ u64 fadd2(u64 a, u64 b) {
    u64 d; asm("add.rn.f32x2 %0,%1,%2;" : "=l"(d) : "l"(a), "l"(b)); return d;
}
__device__ __forceinline__ float ex2f(float x) {
    float r; asm("ex2.approx.f32 %0,%1;" : "=f"(r) : "f"(x)); return r;
}
__device__ __forceinline__ u64 shfl_xor_u64(u64 v, int m) {
    unsigned lo = (unsigned)v, hi = (unsigned)(v >> 32);
    lo = __shfl_xor_sync(0xffffffffu, lo, m);
    hi = __shfl_xor_sync(0xffffffffu, hi, m);
    return ((u64)hi << 32) | lo;
}

struct Params {
    const int   *dt, *ds, *sl;
    const float *emb_dice, *emb_star, *emb_btns;
    const float *Wqkv[2], *bqkv[2], *Wo[2], *bo[2], *Wl[2], *bl[2];
    const float *Wout, *bout;
    float *out;
    int B;
};

// Warp-uniform weights -> constant bank (ULDC path).
struct __align__(16) GC {
    u64x2 Wq1[12][4];    // layer-1 Wqkv row pairs; q rows pre-scaled by S
    u64   bq1[12];
    u64x2 Wo2[2][4][4];  // row pairs (2p, 2p+1)
    u64   bo2[2][4];
    u64x2 Wl2[2][4][4];
    u64   bl2[2][4];
};
__constant__ GC gcw;
__device__ GC g_gc;      // prep output, memcpy'd into gcw

// Per-lane-indexed tables -> shared (staged per block).
struct __align__(16) GW {
    u64 Wexp[32][33];    // [id_k][id_q] packed per-head exp'd scores; 33-stride de-banks
    u64 t0v[32][4];      // layer-0 v pairs {v_h0[i], v_h1[i]}
    u64 embp[32][6];     // x pairs (48B stride)
    u64 Wout2[20][4];    // pre-scaled by 1/15
    float bout[20];
    float pad[4];
};
__device__ GW g_w;
__device__ u64 g_q0[32][4];   // prep staging
__device__ u64 g_k0[32][4];

__global__ void prep_kernel(Params p) {
    const int i = threadIdx.x;
    const float S = 0.72134752f;   // 0.5 * log2(e)

    // ---------- phase 1 ----------
    if (i < 384) {
        int id = i / 12, pp = i % 12;
        int gg = pp >> 2, r = pp & 3;
        int r0 = gg * 8 + r, r1 = r0 + 4;
        const float *e = (id < 15) ? p.emb_dice + id * 8
                        : (id < 30) ? p.emb_star + (id - 15) * 8
                                    : p.emb_btns + (id - 30) * 8;
        const float *w0 = p.Wqkv[0] + r0 * 8;
        const float *w1 = p.Wqkv[0] + r1 * 8;
        u64 acc = pk2(p.bqkv[0][r0], p.bqkv[0][r1]);
        #pragma unroll
        for (int j = 0; j < 8; j++)
            acc = ffma2(pk2(e[j], e[j]), pk2(w0[j], w1[j]), acc);
        if (pp < 4)      g_q0[id][pp]     = fmul2(acc, pk2(S, S));
        else if (pp < 8) g_k0[id][pp - 4] = acc;
        else             g_w.t0v[id][pp - 8] = acc;
    } else if (i < 480) {            // Wq1 (q rows S-scaled)
        int k = i - 384; int pp = k >> 3, j = k & 7;
        int gg = pp >> 2, r = pp & 3, r0 = gg * 8 + r, r1 = r0 + 4;
        u64 w = pk2(p.Wqkv[1][r0 * 8 + j], p.Wqkv[1][r1 * 8 + j]);
        if (pp < 4) w = fmul2(w, pk2(S, S));
        ((u64 *)g_gc.Wq1)[pp * 8 + j] = w;
    } else if (i < 492) {            // bq1
        int pp = i - 480; int gg = pp >> 2, r = pp & 3, r0 = gg * 8 + r;
        u64 w = pk2(p.bqkv[1][r0], p.bqkv[1][r0 + 4]);
        if (pp < 4) w = fmul2(w, pk2(S, S));
        g_gc.bq1[pp] = w;
    } else if (i < 556) {            // Wo2 (flat [l][pr][j])
        int k = i - 492; int l = k >> 5, pr = (k >> 3) & 3, j = k & 7;
        ((u64 *)g_gc.Wo2)[k] = pk2(p.Wo[l][2 * pr * 8 + j], p.Wo[l][(2 * pr + 1) * 8 + j]);
    } else if (i < 564) {            // bo2
        int k = i - 556; int l = k >> 2, pr = k & 3;
        g_gc.bo2[l][pr] = pk2(p.bo[l][2 * pr], p.bo[l][2 * pr + 1]);
    } else if (i < 628) {            // Wl2
        int k = i - 564; int l = k >> 5, pr = (k >> 3) & 3, j = k & 7;
        ((u64 *)g_gc.Wl2)[k] = pk2(p.Wl[l][2 * pr * 8 + j], p.Wl[l][(2 * pr + 1) * 8 + j]);
    } else if (i < 636) {            // bl2
        int k = i - 628; int l = k >> 2, pr = k & 3;
        g_gc.bl2[l][pr] = pk2(p.bl[l][2 * pr], p.bl[l][2 * pr + 1]);
    } else if (i < 716) {            // Wout2 pre-scaled by 1/15
        int k = i - 636; int a = k >> 2, j = k & 3;
        const float m = 1.0f / 15.0f;
        g_w.Wout2[a][j] = pk2(p.Wout[a * 8 + 2 * j] * m, p.Wout[a * 8 + 2 * j + 1] * m);
    } else if (i < 736) {
        g_w.bout[i - 716] = p.bout[i - 716];
    } else if (i < 992) {            // embp
        int k = i - 736; int id = k >> 3, j = k & 7;
        const float *e = (id < 15) ? p.emb_dice + id * 8
                        : (id < 30) ? p.emb_star + (id - 15) * 8
                                    : p.emb_btns + (id - 30) * 8;
        ((float *)g_w.embp[id])[j] = e[j];
    }
    __syncthreads();

    // ---------- phase 2: Wexp ----------
    {
        int a = i >> 5, b = i & 31;   // a = query id, b = key id
        u64 s2 = 0;
        #pragma unroll
        for (int j = 0; j < 4; j++)
            s2 = ffma2(g_q0[a][j], g_k0[b][j], s2);
        float s0, s1; upk2(s2, s0, s1);
        g_w.Wexp[b][a] = pk2(ex2f(s0), ex2f(s1));
    }
}

// o-proj + residual + MLP + residual; weights from constant bank (l literal).
__device__ __forceinline__ void ff1(const float *o, float *x, const int l) {
    u64 od[8];
    #pragma unroll
    for (int i = 0; i < 8; i++) od[i] = pk2(o[i], o[i]);
    float xo[8];
    #pragma unroll
    for (int pr = 0; pr < 4; pr++) {
        u64x2 w01 = gcw.Wo2[l][pr][0], w23 = gcw.Wo2[l][pr][1];
        u64x2 w45 = gcw.Wo2[l][pr][2], w67 = gcw.Wo2[l][pr][3];
        u64 acc = ffma2(od[0], w01.x, gcw.bo2[l][pr]);
        acc = ffma2(od[1], w01.y, acc); acc = ffma2(od[2], w23.x, acc);
        acc = ffma2(od[3], w23.y, acc); acc = ffma2(od[4], w45.x, acc);
        acc = ffma2(od[5], w45.y, acc); acc = ffma2(od[6], w67.x, acc);
        acc = ffma2(od[7], w67.y, acc);
        float r0, r1; upk2(acc, r0, r1);
        xo[2 * pr] = x[2 * pr] + r0; xo[2 * pr + 1] = x[2 * pr + 1] + r1;
    }
    u64 xd[8];
    #pragma unroll
    for (int i = 0; i < 8; i++) xd[i] = pk2(xo[i], xo[i]);
    #pragma unroll
    for (int pr = 0; pr < 4; pr++) {
        u64x2 w01 = gcw.Wl2[l][pr][0], w23 = gcw.Wl2[l][pr][1];
        u64x2 w45 = gcw.Wl2[l][pr][2], w67 = gcw.Wl2[l][pr][3];
        u64 acc = ffma2(xd[0], w01.x, gcw.bl2[l][pr]);
        acc = ffma2(xd[1], w01.y, acc); acc = ffma2(xd[2], w23.x, acc);
        acc = ffma2(xd[3], w23.y, acc); acc = ffma2(xd[4], w45.x, acc);
        acc = ffma2(xd[5], w45.y, acc); acc = ffma2(xd[6], w67.x, acc);
        acc = ffma2(xd[7], w67.y, acc);
        float r0, r1; upk2(acc, r0, r1);
        x[2 * pr]     = xo[2 * pr]     + fmaxf(r0, 0.f);
        x[2 * pr + 1] = xo[2 * pr + 1] + fmaxf(r1, 0.f);
    }
}

__global__ void __launch_bounds__(TPB, 4) bot_kernel(Params p) {
    __shared__ __align__(16) GW sw;                       // ~12 KB
    // layer-1 kv: [warp][half][168 u64]; half stride 1344 B (%128==64 ->
    // conflict-free vs other half). token row = 10 u64: k01,k23,v01,v23,pad2.
    __shared__ __align__(16) u64 kvs[NW][2][168];         // 21504 B
    __shared__ __align__(16) unsigned char idsb[NW][2][16];

    const int tid = threadIdx.x;
    {
        const u64x2 *src = (const u64x2 *)&g_w;
        u64x2 *dst = (u64x2 *)&sw;
        #pragma unroll
        for (int k = 0; k < 3; k++) {
            int i = tid + k * TPB;
            if (i < (int)(sizeof(GW) / 16)) dst[i] = src[i];
        }
    }
    __syncthreads();

    const int warp = tid >> 5, lane = tid & 31;
    const int half = lane >> 4, s = lane & 15;
    const int b = blockIdx.x * SPB + warp * 2 + half;
    const bool tok = (s < 15);

    int id = 0;   // lane-15 dummy (slot 15 never read)
    if (tok) {
        const int base = b * 5;
        id = (s < 5) ? p.dt[base + s]
           : (s < 10) ? 15 + p.ds[base + s - 5]
                      : 30 + p.sl[base + s - 10];
    }
    idsb[warp][half][s] = (unsigned char)id;
    __syncwarp();
    const uint4 idw = *(const uint4 *)&idsb[warp][half][0];

    float x[8];
    {
        const u64x2 *e = (const u64x2 *)&sw.embp[id][0];
        u64x2 e01 = e[0], e23 = e[1];
        upk2(e01.x, x[0], x[1]); upk2(e01.y, x[2], x[3]);
        upk2(e23.x, x[4], x[5]); upk2(e23.y, x[6], x[7]);
    }

    // ---- layer 0 attention: pure table reads, no q/k ----
    {
        u64 sum2 = 0, av0 = 0, av1 = 0, av2 = 0, av3 = 0;
        #pragma unroll
        for (int t = 0; t < 15; t++) {
            unsigned idt = ((&idw.x)[t >> 2] >> ((t & 3) * 8)) & 0xFF;
            const u64 *wrow = (const u64 *)((const char *)sw.Wexp + idt * 264);
            u64 w = wrow[id];                       // LDS.64 gather by own id
            const u64x2 *vp = (const u64x2 *)sw.t0v[idt];
            u64x2 v01 = vp[0], v23 = vp[1];         // half-uniform broadcast
            sum2 = fadd2(sum2, w);
            av0 = ffma2(w, v01.x, av0); av1 = ffma2(w, v01.y, av1);
            av2 = ffma2(w, v23.x, av2); av3 = ffma2(w, v23.y, av3);
        }
        float s0, s1; upk2(sum2, s0, s1);
        u64 inv = pk2(__fdividef(1.f, s0), __fdividef(1.f, s1));
        float o[8];
        { u64 t = fmul2(av0, inv); upk2(t, o[0], o[4]); }
        { u64 t = fmul2(av1, inv); upk2(t, o[1], o[5]); }
        { u64 t = fmul2(av2, inv); upk2(t, o[2], o[6]); }
        { u64 t = fmul2(av3, inv); upk2(t, o[3], o[7]); }
        ff1(o, x, 0);
    }

    // ---- layer 1: qkv gemv (constant weights) -> kv exchange -> attention ----
    u64 *kvh = &kvs[warp][half][0];
    u64 *row = kvh + s * 10;
    u64 q2[4];
    {
        u64 xd[8];
        #pragma unroll
        for (int i = 0; i < 8; i++) xd[i] = pk2(x[i], x[i]);
        u64 hold = 0;
        #pragma unroll
        for (int pr = 0; pr < 12; pr++) {
            u64x2 w01 = gcw.Wq1[pr][0], w23 = gcw.Wq1[pr][1];
            u64x2 w45 = gcw.Wq1[pr][2], w67 = gcw.Wq1[pr][3];
            u64 a = ffma2(xd[0], w01.x, gcw.bq1[pr]);
            a = ffma2(xd[1], w01.y, a); a = ffma2(xd[2], w23.x, a);
            a = ffma2(xd[3], w23.y, a); a = ffma2(xd[4], w45.x, a);
            a = ffma2(xd[5], w45.y, a); a = ffma2(xd[6], w67.x, a);
            a = ffma2(xd[7], w67.y, a);
            if (pr < 4) q2[pr] = a;
            else if ((pr & 1) == 0) hold = a;
            else if (tok) {
                u64x2 st; st.x = hold; st.y = a;
                *(u64x2 *)(row + (pr - 5)) = st;   // offsets 0,2,4,6
            }
        }
    }
    __syncwarp();   // kv writes -> kv reads
    {
        u64 sum2 = 0, av0 = 0, av1 = 0, av2 = 0, av3 = 0;
        #pragma unroll
        for (int t = 0; t < 15; t++) {
            const u64 *r = kvh + t * 10;
            u64x2 k01 = *(const u64x2 *)(r);
            u64x2 k23 = *(const u64x2 *)(r + 2);
            u64 s2 = fmul2(q2[0], k01.x);
            s2 = ffma2(q2[1], k01.y, s2);
            s2 = ffma2(q2[2], k23.x, s2);
            s2 = ffma2(q2[3], k23.y, s2);
            float f0, f1; upk2(s2, f0, f1);
            u64 w = pk2(ex2f(f0), ex2f(f1));
            u64x2 v01 = *(const u64x2 *)(r + 4);
            u64x2 v23 = *(const u64x2 *)(r + 6);
            sum2 = fadd2(sum2, w);
            av0 = ffma2(w, v01.x, av0); av1 = ffma2(w, v01.y, av1);
            av2 = ffma2(w, v23.x, av2); av3 = ffma2(w, v23.y, av3);
        }
        float s0, s1; upk2(sum2, s0, s1);
        u64 inv = pk2(__fdividef(1.f, s0), __fdividef(1.f, s1));
        float o[8];
        { u64 t = fmul2(av0, inv); upk2(t, o[0], o[4]); }
        { u64 t = fmul2(av1, inv); upk2(t, o[1], o[5]); }
        { u64 t = fmul2(av2, inv); upk2(t, o[2], o[6]); }
        { u64 t = fmul2(av3, inv); upk2(t, o[3], o[7]); }
        ff1(o, x, 1);
    }

    // ---- sum over 15 tokens in pair domain (1/15 folded into Wout) ----
    u64 xq[4];
    #pragma unroll
    for (int i = 0; i < 4; i++) {
        u64 v = tok ? pk2(x[2 * i], x[2 * i + 1]) : 0;
        v = fadd2(v, shfl_xor_u64(v, 1));
        v = fadd2(v, shfl_xor_u64(v, 2));
        v = fadd2(v, shfl_xor_u64(v, 4));
        v = fadd2(v, shfl_xor_u64(v, 8));
        xq[i] = v;
    }

    // ---- output projection ----
    if (b < p.B) {
        {
            const u64x2 *wp = (const u64x2 *)sw.Wout2[s];
            u64x2 w01 = wp[0], w23 = wp[1];
            u64 acc = fmul2(xq[0], w01.x);
            acc = ffma2(xq[1], w01.y, acc);
            acc = ffma2(xq[2], w23.x, acc);
            acc = ffma2(xq[3], w23.y, acc);
            float r0, r1; upk2(acc, r0, r1);
            p.out[b * 20 + s] = sw.bout[s] + r0 + r1;
        }
        if (s < 4) {
            const int a = s + 16;
            const u64x2 *wp = (const u64x2 *)sw.Wout2[a];
            u64x2 w01 = wp[0], w23 = wp[1];
            u64 acc = fmul2(xq[0], w01.x);
            acc = ffma2(xq[1], w01.y, acc);
            acc = ffma2(xq[2], w23.x, acc);
            acc = ffma2(xq[3], w23.y, acc);
            float r0, r1; upk2(acc, r0, r1);
            p.out[b * 20 + a] = sw.bout[a] + r0 + r1;
        }
    }
}

extern "C" void kernel_launch(void* const* d_in, const int* in_sizes, int n_in,
                              void* d_out, int out_size) {
    Params p;
    p.dt = (const int *)d_in[0];
    p.ds = (const int *)d_in[1];
    p.sl = (const int *)d_in[2];
    p.emb_dice = (const float *)d_in[3];
    p.emb_star = (const float *)d_in[4];
    p.emb_btns = (const float *)d_in[5];

    int layer_base, wout_i, bout_i;
    if (in_sizes[6] == 160) { wout_i = 6; bout_i = 7; layer_base = 8; }
    else                    { layer_base = 6; wout_i = 18; bout_i = 19; }

    for (int l = 0; l < 2; l++) {
        int o = layer_base + 6 * l;
        p.Wqkv[l] = (const float *)d_in[o];
        p.bqkv[l] = (const float *)d_in[o + 1];
        p.Wo[l]   = (const float *)d_in[o + 2];
        p.bo[l]   = (const float *)d_in[o + 3];
        p.Wl[l]   = (const float *)d_in[o + 4];
        p.bl[l]   = (const float *)d_in[o + 5];
    }
    p.Wout = (const float *)d_in[wout_i];
    p.bout = (const float *)d_in[bout_i];
    p.out  = (float *)d_out;
    p.B    = in_sizes[0] / 5;

    prep_kernel<<<1, 1024>>>(p);

    // D2D copy of packed uniform weights into the constant bank (capturable).
    void *gc_src = nullptr;
    cudaGetSymbolAddress(&gc_src, g_gc);
    cudaMemcpyToSymbolAsync(gcw, gc_src, sizeof(GC), 0, cudaMemcpyDeviceToDevice, 0);

    int blocks = (p.B + SPB - 1) / SPB;
    bot_kernel<<<blocks, TPB>>>(p);
}

// round 16
// speedup vs baseline: 1.3232x; 1.0304x over previous
#include <cuda_runtime.h>

// BetterBot round-16: R15 (best main, 50.1us) + __launch_bounds__(256,5)
// (51-reg cap -> 40 warps/SM) + rcp.approx normalization. Nothing else.

#define TPB 256
#define NW  8
#define SPB 16   // samples per block

typedef unsigned long long u64;
typedef ulonglong2 u64x2;

__device__ __forceinline__ u64 pk2(float lo, float hi) {
    u64 r; asm("mov.b64 %0,{%1,%2};" : "=l"(r) : "f"(lo), "f"(hi)); return r;
}
__device__ __forceinline__ void upk2(u64 v, float &lo, float &hi) {
    asm("mov.b64 {%0,%1},%2;" : "=f"(lo), "=f"(hi) : "l"(v));
}
__device__ __forceinline__ u64 ffma2(u64 a, u64 b, u64 c) {
    u64 d; asm("fma.rn.f32x2 %0,%1,%2,%3;" : "=l"(d) : "l"(a), "l"(b), "l"(c)); return d;
}
__device__ __forceinline__ u64 fmul2(u64 a, u64 b) {
    u64 d; asm("mul.rn.f32x2 %0,%1,%2;" : "=l"(d) : "l"(a), "l"(b)); return d;
}
__device__ __forceinline__ u64 fadd2(u64 a, u64 b) {
    u64 d; asm("add.rn.f32x2 %0,%1,%2;" : "=l"(d) : "l"(a), "l"(b)); return d;
}
__device__ __forceinline__ float ex2f(float x) {
    float r; asm("ex2.approx.f32 %0,%1;" : "=f"(r) : "f"(x)); return r;
}
__device__ __forceinline__ float rcpf(float x) {
    float r; asm("rcp.approx.f32 %0,%1;" : "=f"(r) : "f"(x)); return r;
}
__device__ __forceinline__ u64 shfl_xor_u64(u64 v, int m) {
    unsigned lo = (unsigned)v, hi = (unsigned)(v >> 32);
    lo = __shfl_xor_sync(0xffffffffu, lo, m);
    hi = __shfl_xor_sync(0xffffffffu, hi, m);
    return ((u64)hi << 32) | lo;
}

struct Params {
    const int   *dt, *ds, *sl;
    const float *emb_dice, *emb_star, *emb_btns;
    const float *Wqkv[2], *bqkv[2], *Wo[2], *bo[2], *Wl[2], *bl[2];
    const float *Wout, *bout;
    float *out;
    int B;
};

// Warp-uniform weights -> constant bank (ULDC path).
struct __align__(16) GC {
    u64x2 Wq1[12][4];    // layer-1 Wqkv row pairs; q rows pre-scaled by S
    u64   bq1[12];
    u64x2 Wo2[2][4][4];  // row pairs (2p, 2p+1)
    u64   bo2[2][4];
    u64x2 Wl2[2][4][4];
    u64   bl2[2][4];
};
__constant__ GC gcw;
__device__ GC g_gc;      // prep output, memcpy'd into gcw

// Per-lane-indexed tables -> shared (staged per block).
struct __align__(16) GW {
    u64 Wexp[32][33];    // [id_k][id_q] packed per-head exp'd scores; 33-stride de-banks
    u64 t0v[32][4];      // layer-0 v pairs {v_h0[i], v_h1[i]}
    u64 embp[32][6];     // x pairs (48B stride)
    u64 Wout2[20][4];    // pre-scaled by 1/15
    float bout[20];
    float pad[4];
};
__device__ GW g_w;
__device__ u64 g_q0[32][4];   // prep staging
__device__ u64 g_k0[32][4];

__global__ void prep_kernel(Params p) {
    const int i = threadIdx.x;
    const float S = 0.72134752f;   // 0.5 * log2(e)

    // ---------- phase 1 ----------
    if (i < 384) {
        int id = i / 12, pp = i % 12;
        int gg = pp >> 2, r = pp & 3;
        int r0 = gg * 8 + r, r1 = r0 + 4;
        const float *e = (id < 15) ? p.emb_dice + id * 8
                        : (id < 30) ? p.emb_star + (id - 15) * 8
                                    : p.emb_btns + (id - 30) * 8;
        const float *w0 = p.Wqkv[0] + r0 * 8;
        const float *w1 = p.Wqkv[0] + r1 * 8;
        u64 acc = pk2(p.bqkv[0][r0], p.bqkv[0][r1]);
        #pragma unroll
        for (int j = 0; j < 8; j++)
            acc = ffma2(pk2(e[j], e[j]), pk2(w0[j], w1[j]), acc);
        if (pp < 4)      g_q0[id][pp]     = fmul2(acc, pk2(S, S));
        else if (pp < 8) g_k0[id][pp - 4] = acc;
        else             g_w.t0v[id][pp - 8] = acc;
    } else if (i < 480) {            // Wq1 (q rows S-scaled)
        int k = i - 384; int pp = k >> 3, j = k & 7;
        int gg = pp >> 2, r = pp & 3, r0 = gg * 8 + r, r1 = r0 + 4;
        u64 w = pk2(p.Wqkv[1][r0 * 8 + j], p.Wqkv[1][r1 * 8 + j]);
        if (pp < 4) w = fmul2(w, pk2(S, S));
        ((u64 *)g_gc.Wq1)[pp * 8 + j] = w;
    } else if (i < 492) {            // bq1
        int pp = i - 480; int gg = pp >> 2, r = pp & 3, r0 = gg * 8 + r;
        u64 w = pk2(p.bqkv[1][r0], p.bqkv[1][r0 + 4]);
        if (pp < 4) w = fmul2(w, pk2(S, S));
        g_gc.bq1[pp] = w;
    } else if (i < 556) {            // Wo2 (flat [l][pr][j])
        int k = i - 492; int l = k >> 5, pr = (k >> 3) & 3, j = k & 7;
        ((u64 *)g_gc.Wo2)[k] = pk2(p.Wo[l][2 * pr * 8 + j], p.Wo[l][(2 * pr + 1) * 8 + j]);
    } else if (i < 564) {            // bo2
        int k = i - 556; int l = k >> 2, pr = k & 3;
        g_gc.bo2[l][pr] = pk2(p.bo[l][2 * pr], p.bo[l][2 * pr + 1]);
    } else if (i < 628) {            // Wl2
        int k = i - 564; int l = k >> 5, pr = (k >> 3) & 3, j = k & 7;
        ((u64 *)g_gc.Wl2)[k] = pk2(p.Wl[l][2 * pr * 8 + j], p.Wl[l][(2 * pr + 1) * 8 + j]);
    } else if (i < 636) {            // bl2
        int k = i - 628; int l = k >> 2, pr = k & 3;
        g_gc.bl2[l][pr] = pk2(p.bl[l][2 * pr], p.bl[l][2 * pr + 1]);
    } else if (i < 716) {            // Wout2 pre-scaled by 1/15
        int k = i - 636; int a = k >> 2, j = k & 3;
        const float m = 1.0f / 15.0f;
        g_w.Wout2[a][j] = pk2(p.Wout[a * 8 + 2 * j] * m, p.Wout[a * 8 + 2 * j + 1] * m);
    } else if (i < 736) {
        g_w.bout[i - 716] = p.bout[i - 716];
    } else if (i < 992) {            // embp
        int k = i - 736; int id = k >> 3, j = k & 7;
        const float *e = (id < 15) ? p.emb_dice + id * 8
                        : (id < 30) ? p.emb_star + (id - 15) * 8
                                    : p.emb_btns + (id - 30) * 8;
        ((float *)g_w.embp[id])[j] = e[j];
    }
    __syncthreads();

    // ---------- phase 2: Wexp ----------
    {
        int a = i >> 5, b = i & 31;   // a = query id, b = key id
        u64 s2 = 0;
        #pragma unroll
        for (int j = 0; j < 4; j++)
            s2 = ffma2(g_q0[a][j], g_k0[b][j], s2);
        float s0, s1; upk2(s2, s0, s1);
        g_w.Wexp[b][a] = pk2(ex2f(s0), ex2f(s1));
    }
}

// o-proj + residual + MLP + residual; weights from constant bank (l literal).
__device__ __forceinline__ void ff1(const float *o, float *x, const int l) {
    u64 od[8];
    #pragma unroll
    for (int i = 0; i < 8; i++) od[i] = pk2(o[i], o[i]);
    float xo[8];
    #pragma unroll
    for (int pr = 0; pr < 4; pr++) {
        u64x2 w01 = gcw.Wo2[l][pr][0], w23 = gcw.Wo2[l][pr][1];
        u64x2 w45 = gcw.Wo2[l][pr][2], w67 = gcw.Wo2[l][pr][3];
        u64 acc = ffma2(od[0], w01.x, gcw.bo2[l][pr]);
        acc = ffma2(od[1], w01.y, acc); acc = ffma2(od[2], w23.x, acc);
        acc = ffma2(od[3], w23.y, acc); acc = ffma2(od[4], w45.x, acc);
        acc = ffma2(od[5], w45.y, acc); acc = ffma2(od[6], w67.x, acc);
        acc = ffma2(od[7], w67.y, acc);
        float r0, r1; upk2(acc, r0, r1);
        xo[2 * pr] = x[2 * pr] + r0; xo[2 * pr + 1] = x[2 * pr + 1] + r1;
    }
    u64 xd[8];
    #pragma unroll
    for (int i = 0; i < 8; i++) xd[i] = pk2(xo[i], xo[i]);
    #pragma unroll
    for (int pr = 0; pr < 4; pr++) {
        u64x2 w01 = gcw.Wl2[l][pr][0], w23 = gcw.Wl2[l][pr][1];
        u64x2 w45 = gcw.Wl2[l][pr][2], w67 = gcw.Wl2[l][pr][3];
        u64 acc = ffma2(xd[0], w01.x, gcw.bl2[l][pr]);
        acc = ffma2(xd[1], w01.y, acc); acc = ffma2(xd[2], w23.x, acc);
        acc = ffma2(xd[3], w23.y, acc); acc = ffma2(xd[4], w45.x, acc);
        acc = ffma2(xd[5], w45.y, acc); acc = ffma2(xd[6], w67.x, acc);
        acc = ffma2(xd[7], w67.y, acc);
        float r0, r1; upk2(acc, r0, r1);
        x[2 * pr]     = xo[2 * pr]     + fmaxf(r0, 0.f);
        x[2 * pr + 1] = xo[2 * pr + 1] + fmaxf(r1, 0.f);
    }
}

__global__ void __launch_bounds__(TPB, 5) bot_kernel(Params p) {
    __shared__ __align__(16) GW sw;                       // ~12 KB
    // layer-1 kv: [warp][half][168 u64]; half stride 1344 B (%128==64 ->
    // conflict-free vs other half). token row = 10 u64: k01,k23,v01,v23,pad2.
    __shared__ __align__(16) u64 kvs[NW][2][168];         // 21504 B
    __shared__ __align__(16) unsigned char idsb[NW][2][16];

    const int tid = threadIdx.x;
    {
        const u64x2 *src = (const u64x2 *)&g_w;
        u64x2 *dst = (u64x2 *)&sw;
        #pragma unroll
        for (int k = 0; k < 3; k++) {
            int i = tid + k * TPB;
            if (i < (int)(sizeof(GW) / 16)) dst[i] = src[i];
        }
    }
    __syncthreads();

    const int warp = tid >> 5, lane = tid & 31;
    const int half = lane >> 4, s = lane & 15;
    const int b = blockIdx.x * SPB + warp * 2 + half;
    const bool tok = (s < 15);

    int id = 0;   // lane-15 dummy (slot 15 never read)
    if (tok) {
        const int base = b * 5;
        id = (s < 5) ? p.dt[base + s]
           : (s < 10) ? 15 + p.ds[base + s - 5]
                      : 30 + p.sl[base + s - 10];
    }
    idsb[warp][half][s] = (unsigned char)id;
    __syncwarp();
    const uint4 idw = *(const uint4 *)&idsb[warp][half][0];

    float x[8];
    {
        const u64x2 *e = (const u64x2 *)&sw.embp[id][0];
        u64x2 e01 = e[0], e23 = e[1];
        upk2(e01.x, x[0], x[1]); upk2(e01.y, x[2], x[3]);
        upk2(e23.x, x[4], x[5]); upk2(e23.y, x[6], x[7]);
    }

    // ---- layer 0 attention: pure table reads, no q/k ----
    {
        u64 sum2 = 0, av0 = 0, av1 = 0, av2 = 0, av3 = 0;
        #pragma unroll
        for (int t = 0; t < 15; t++) {
            unsigned idt = ((&idw.x)[t >> 2] >> ((t & 3) * 8)) & 0xFF;
            const u64 *wrow = (const u64 *)((const char *)sw.Wexp + idt * 264);
            u64 w = wrow[id];                       // LDS.64 gather by own id
            const u64x2 *vp = (const u64x2 *)sw.t0v[idt];
            u64x2 v01 = vp[0], v23 = vp[1];         // half-uniform broadcast
            sum2 = fadd2(sum2, w);
            av0 = ffma2(w, v01.x, av0); av1 = ffma2(w, v01.y, av1);
            av2 = ffma2(w, v23.x, av2); av3 = ffma2(w, v23.y, av3);
        }
        float s0, s1; upk2(sum2, s0, s1);
        u64 inv = pk2(rcpf(s0), rcpf(s1));
        float o[8];
        { u64 t = fmul2(av0, inv); upk2(t, o[0], o[4]); }
        { u64 t = fmul2(av1, inv); upk2(t, o[1], o[5]); }
        { u64 t = fmul2(av2, inv); upk2(t, o[2], o[6]); }
        { u64 t = fmul2(av3, inv); upk2(t, o[3], o[7]); }
        ff1(o, x, 0);
    }

    // ---- layer 1: qkv gemv (constant weights) -> kv exchange -> attention ----
    u64 *kvh = &kvs[warp][half][0];
    u64 *row = kvh + s * 10;
    u64 q2[4];
    {
        u64 xd[8];
        #pragma unroll
        for (int i = 0; i < 8; i++) xd[i] = pk2(x[i], x[i]);
        u64 hold = 0;
        #pragma unroll
        for (int pr = 0; pr < 12; pr++) {
            u64x2 w01 = gcw.Wq1[pr][0], w23 = gcw.Wq1[pr][1];
            u64x2 w45 = gcw.Wq1[pr][2], w67 = gcw.Wq1[pr][3];
            u64 a = ffma2(xd[0], w01.x, gcw.bq1[pr]);
            a = ffma2(xd[1], w01.y, a); a = ffma2(xd[2], w23.x, a);
            a = ffma2(xd[3], w23.y, a); a = ffma2(xd[4], w45.x, a);
            a = ffma2(xd[5], w45.y, a); a = ffma2(xd[6], w67.x, a);
            a = ffma2(xd[7], w67.y, a);
            if (pr < 4) q2[pr] = a;
            else if ((pr & 1) == 0) hold = a;
            else if (tok) {
                u64x2 st; st.x = hold; st.y = a;
                *(u64x2 *)(row + (pr - 5)) = st;   // offsets 0,2,4,6
            }
        }
    }
    __syncwarp();   // kv writes -> kv reads
    {
        u64 sum2 = 0, av0 = 0, av1 = 0, av2 = 0, av3 = 0;
        #pragma unroll
        for (int t = 0; t < 15; t++) {
            const u64 *r = kvh + t * 10;
            u64x2 k01 = *(const u64x2 *)(r);
            u64x2 k23 = *(const u64x2 *)(r + 2);
            u64 s2 = fmul2(q2[0], k01.x);
            s2 = ffma2(q2[1], k01.y, s2);
            s2 = ffma2(q2[2], k23.x, s2);
            s2 = ffma2(q2[3], k23.y, s2);
            float f0, f1; upk2(s2, f0, f1);
            u64 w = pk2(ex2f(f0), ex2f(f1));
            u64x2 v01 = *(const u64x2 *)(r + 4);
            u64x2 v23 = *(const u64x2 *)(r + 6);
            sum2 = fadd2(sum2, w);
            av0 = ffma2(w, v01.x, av0); av1 = ffma2(w, v01.y, av1);
            av2 = ffma2(w, v23.x, av2); av3 = ffma2(w, v23.y, av3);
        }
        float s0, s1; upk2(sum2, s0, s1);
        u64 inv = pk2(rcpf(s0), rcpf(s1));
        float o[8];
        { u64 t = fmul2(av0, inv); upk2(t, o[0], o[4]); }
        { u64 t = fmul2(av1, inv); upk2(t, o[1], o[5]); }
        { u64 t = fmul2(av2, inv); upk2(t, o[2], o[6]); }
        { u64 t = fmul2(av3, inv); upk2(t, o[3], o[7]); }
        ff1(o, x, 1);
    }

    // ---- sum over 15 tokens in pair domain (1/15 folded into Wout) ----
    u64 xq[4];
    #pragma unroll
    for (int i = 0; i < 4; i++) {
        u64 v = tok ? pk2(x[2 * i], x[2 * i + 1]) : 0;
        v = fadd2(v, shfl_xor_u64(v, 1));
        v = fadd2(v, shfl_xor_u64(v, 2));
        v = fadd2(v, shfl_xor_u64(v, 4));
        v = fadd2(v, shfl_xor_u64(v, 8));
        xq[i] = v;
    }

    // ---- output projection ----
    if (b < p.B) {
        {
            const u64x2 *wp = (const u64x2 *)sw.Wout2[s];
            u64x2 w01 = wp[0], w23 = wp[1];
            u64 acc = fmul2(xq[0], w01.x);
            acc = ffma2(xq[1], w01.y, acc);
            acc = ffma2(xq[2], w23.x, acc);
            acc = ffma2(xq[3], w23.y, acc);
            float r0, r1; upk2(acc, r0, r1);
            p.out[b * 20 + s] = sw.bout[s] + r0 + r1;
        }
        if (s < 4) {
            const int a = s + 16;
            const u64x2 *wp = (const u64x2 *)sw.Wout2[a];
            u64x2 w01 = wp[0], w23 = wp[1];
            u64 acc = fmul2(xq[0], w01.x);
            acc = ffma2(xq[1], w01.y, acc);
            acc = ffma2(xq[2], w23.x, acc);
            acc = ffma2(xq[3], w23.y, acc);
            float r0, r1; upk2(acc, r0, r1);
            p.out[b * 20 + a] = sw.bout[a] + r0 + r1;
        }
    }
}

extern "C" void kernel_launch(void* const* d_in, const int* in_sizes, int n_in,
                              void* d_out, int out_size) {
    Params p;
    p.dt = (const int *)d_in[0];
    p.ds = (const int *)d_in[1];
    p.sl = (const int *)d_in[2];
    p.emb_dice = (const float *)d_in[3];
    p.emb_star = (const float *)d_in[4];
    p.emb_btns = (const float *)d_in[5];

    int layer_base, wout_i, bout_i;
    if (in_sizes[6] == 160) { wout_i = 6; bout_i = 7; layer_base = 8; }
    else                    { layer_base = 6; wout_i = 18; bout_i = 19; }

    for (int l = 0; l < 2; l++) {
        int o = layer_base + 6 * l;
        p.Wqkv[l] = (const float *)d_in[o];
        p.bqkv[l] = (const float *)d_in[o + 1];
        p.Wo[l]   = (const float *)d_in[o + 2];
        p.bo[l]   = (const float *)d_in[o + 3];
        p.Wl[l]   = (const float *)d_in[o + 4];
        p.bl[l]   = (const float *)d_in[o + 5];
    }
    p.Wout = (const float *)d_in[wout_i];
    p.bout = (const float *)d_in[bout_i];
    p.out  = (float *)d_out;
    p.B    = in_sizes[0] / 5;

    prep_kernel<<<1, 1024>>>(p);

    // D2D copy of packed uniform weights into the constant bank (capturable).
    void *gc_src = nullptr;
    cudaGetSymbolAddress(&gc_src, g_gc);
    cudaMemcpyToSymbolAsync(gcw, gc_src, sizeof(GC), 0, cudaMemcpyDeviceToDevice, 0);

    int blocks = (p.B + SPB - 1) / SPB;
    bot_kernel<<<blocks, TPB>>>(p);
}